// round 14
// baseline (speedup 1.0000x reference)
#include <cuda_runtime.h>
#include <cuda_bf16.h>

#define CI 16
#define CO 16
#define DEG 16
#define BSROW (1 + DEG)            // 17 ints per bs_slice row

#define THREADS 128
#define NITER 4
#define PTS_BLK 32                 // 4 iters * 8 point-groups
#define PPAD 49                    // s_part float4 stride per point (49*4 % 32 == 4)

typedef unsigned long long u64;

__device__ __forceinline__ void fma2(u64 &d, u64 a, u64 b) {
    asm("fma.rn.f32x2 %0, %1, %2, %0;" : "+l"(d) : "l"(a), "l"(b));
}
__device__ __forceinline__ u64 add2(u64 a, u64 b) {
    u64 d; asm("add.rn.f32x2 %0, %1, %2;" : "=l"(d) : "l"(a), "l"(b)); return d;
}
__device__ __forceinline__ float2 upk2(u64 v) {
    float2 f; asm("mov.b64 {%0, %1}, %2;" : "=f"(f.x), "=f"(f.y) : "l"(v)); return f;
}

// out[p,o] = sum_j sum_d radii[p*DEG+j,d] * sum_i W[d,o,i] * features[nbr(p,j),i]
// Factored: g_d[i] = sum_j r_jd * f[nbr_j,i];  out[o] = sum_{d,i} W[d,o,i] * g_d[i]
//
// ZERO-SHUFFLE kernel (R13 resized: 32 pts/block -> 29.5 KB smem < 48 KB).
// Phase 1: 16 lanes/pt (q,c4). idx int4 from smem (conflict-free), features +
//   radii LDG prefetched distance-2. Lane accumulates PARTIAL g (its 4
//   neighbors only, 48 FMA) and stores it raw: 3 STS.128 into s_part. No
//   reduction, no cross-lane dependency, no shfl.
// Phase 2: lane=(p16,oh). Per k-quad: load the 4 q-partials (conflict-free
//   padded LDS.128), sum with packed add.rn.f32x2 (FMA pipe), then the
//   broadcast-W fma.rn.f32x2 contraction. Coalesced stores.
__global__ __launch_bounds__(THREADS)
void PeriodicConvolutionPrep_fused(
    const float* __restrict__ features,   // [P, CI]
    const float* __restrict__ radii,      // [P*DEG, 3]
    const float* __restrict__ W,          // [3, CO, CI]
    const int*   __restrict__ bs,         // [P, 1+DEG]
    float*       __restrict__ out,        // [P, CO]
    int P)
{
    __shared__ int    s_bs[PTS_BLK][16];        // 2 KB, stride 16 ints: conflict-free
    __shared__ float4 s_w2[12][16];             // 3 KB: s_w2[d*4+cq][o] = W[d][o][4cq..+3]
    __shared__ float4 s_part[PTS_BLK * PPAD];   // 24.5 KB: partial g, [pt][(q*4+c4)*3+d]

    const int tid  = threadIdx.x;
    const int t16  = tid & 15;
    const int q    = t16 >> 2;           // neighbor quad
    const int c4   = t16 & 3;            // channel quad
    const int pt   = tid >> 4;           // point group (0..7)
    const int wrp  = tid >> 5;
    const int lane = tid & 31;

    const int base   = blockIdx.x * PTS_BLK;
    const int nvalid = min(PTS_BLK, P - base);

    // ---- stage W ----
    {
        const float4* w4 = (const float4*)W;
        for (int t = tid; t < 192; t += THREADS) {
            const int kb = t >> 4, o = t & 15;
            const int d = kb >> 2, cq = kb & 3;
            s_w2[kb][o] = __ldg(w4 + (size_t)d * 64 + o * 4 + cq);
        }
    }
    // ---- stage neighbor indices (drop count column), coalesced ----
    {
        const int* bsrc = bs + (size_t)base * BSROW;
        const int ntot = nvalid * BSROW;
        for (int k = tid; k < ntot; k += THREADS) {
            const int row = k / BSROW, col = k - row * BSROW;
            const int v = __ldg(bsrc + k);
            if (col) s_bs[row][col - 1] = v;
        }
    }

    // ---- point ids ----
    int  p[NITER];
    bool valid[NITER];
#pragma unroll
    for (int it = 0; it < NITER; it++) {
        int pp = base + it * 8 + pt;
        valid[it] = (pp < P);
        p[it] = valid[it] ? pp : (P - 1);
    }

    __syncthreads();

    // ---- distance-2 double-buffered prefetch (idx via smem, no shfl) ----
    float4 fpre[2][4];
    float4 rpre[2][3];
    const float4* fb4 = (const float4*)features;

    auto issue_loads = [&](int it, int slot) {
        const int  ptL = it * 8 + pt;
        const int4 id  = *(const int4*)&s_bs[ptL < nvalid ? ptL : 0][4 * q];
        fpre[slot][0] = __ldg(fb4 + (size_t)id.x * (CI / 4) + c4);
        fpre[slot][1] = __ldg(fb4 + (size_t)id.y * (CI / 4) + c4);
        fpre[slot][2] = __ldg(fb4 + (size_t)id.z * (CI / 4) + c4);
        fpre[slot][3] = __ldg(fb4 + (size_t)id.w * (CI / 4) + c4);
        const float4* rp = (const float4*)(radii + ((size_t)p[it] * DEG + 4 * q) * 3);
        rpre[slot][0] = __ldg(rp + 0);
        rpre[slot][1] = __ldg(rp + 1);
        rpre[slot][2] = __ldg(rp + 2);
    };

    issue_loads(0, 0);
    issue_loads(1, 1);

    // ================= Phase 1: partial g, no reductions =================
#pragma unroll
    for (int it = 0; it < NITER; it++) {
        const int slot = it & 1;

        const float4 f0 = fpre[slot][0];
        const float4 f1 = fpre[slot][1];
        const float4 f2 = fpre[slot][2];
        const float4 f3 = fpre[slot][3];
        const float4 rv0 = rpre[slot][0];
        const float4 rv1 = rpre[slot][1];
        const float4 rv2 = rpre[slot][2];
        const float r[12] = { rv0.x, rv0.y, rv0.z, rv0.w, rv1.x, rv1.y,
                              rv1.z, rv1.w, rv2.x, rv2.y, rv2.z, rv2.w };

        float g[12];
#pragma unroll
        for (int d = 0; d < 3; d++) {
            g[d * 4 + 0] = r[0 * 3 + d] * f0.x;
            g[d * 4 + 1] = r[0 * 3 + d] * f0.y;
            g[d * 4 + 2] = r[0 * 3 + d] * f0.z;
            g[d * 4 + 3] = r[0 * 3 + d] * f0.w;
            g[d * 4 + 0] = fmaf(r[1 * 3 + d], f1.x, g[d * 4 + 0]);
            g[d * 4 + 1] = fmaf(r[1 * 3 + d], f1.y, g[d * 4 + 1]);
            g[d * 4 + 2] = fmaf(r[1 * 3 + d], f1.z, g[d * 4 + 2]);
            g[d * 4 + 3] = fmaf(r[1 * 3 + d], f1.w, g[d * 4 + 3]);
            g[d * 4 + 0] = fmaf(r[2 * 3 + d], f2.x, g[d * 4 + 0]);
            g[d * 4 + 1] = fmaf(r[2 * 3 + d], f2.y, g[d * 4 + 1]);
            g[d * 4 + 2] = fmaf(r[2 * 3 + d], f2.z, g[d * 4 + 2]);
            g[d * 4 + 3] = fmaf(r[2 * 3 + d], f2.w, g[d * 4 + 3]);
            g[d * 4 + 0] = fmaf(r[3 * 3 + d], f3.x, g[d * 4 + 0]);
            g[d * 4 + 1] = fmaf(r[3 * 3 + d], f3.y, g[d * 4 + 1]);
            g[d * 4 + 2] = fmaf(r[3 * 3 + d], f3.z, g[d * 4 + 2]);
            g[d * 4 + 3] = fmaf(r[3 * 3 + d], f3.w, g[d * 4 + 3]);
        }

        if (it + 2 < NITER)
            issue_loads(it + 2, slot);

        // store raw partial: 3 STS.128, conflict-free phases (stride 12 words)
        if (valid[it]) {
            float4* pp = &s_part[(it * 8 + pt) * PPAD + t16 * 3];
            pp[0] = make_float4(g[0], g[1], g[2],  g[3]);
            pp[1] = make_float4(g[4], g[5], g[6],  g[7]);
            pp[2] = make_float4(g[8], g[9], g[10], g[11]);
        }
    }

    __syncthreads();

    // ============ Phase 2: fold partials (add2) + contraction (fma2) ============
    // 32 points, 64 (point, o-half) pairs -> warps 0,1 each handle 16 points x 2 halves
    {
        const int p16 = lane & 15;
        const int oh  = lane >> 4;
        const int pL  = (wrp & 1) * 16 + p16;   // warps 0,2 -> pts 0-15; 1,3 -> 16-31
        const bool active = (wrp < 2) ? true : false;

        // warps 0-1 cover all 32 points (both halves via oh); warps 2-3 idle here.
        // To use all 4 warps: warps 0-1 take oh as is; warps 2-3 take the other
        // 16-point group with the same oh mapping.
        const int pL2 = (wrp >> 1) ? (16 + ((wrp & 1) * 0 + p16)) : p16;
        const int myP = (wrp < 2) ? ((wrp & 1) * 16 + p16) : pL2;
        (void)pL; (void)active;

        // Simpler exact cover: warp w handles points [w*8, w*8+8) x both halves? No:
        // each warp has 32 lanes = 16 points x 2 halves. 4 warps x 16 = 64 slots;
        // 32 points x 2 halves = 64 work items. Map: warp w -> points (w&1)*16+p16? 
        // warps 0,1 cover pts 0..31 fully (oh 0/1). warps 2,3 duplicate -> mask off.
        if (wrp < 2) {
            const int pp2 = (wrp * 16) + p16;
            if (pp2 < nvalid) {
                const float4* gp = &s_part[pp2 * PPAD];

                u64 acc[8];
#pragma unroll
                for (int oo = 0; oo < 8; oo++) acc[oo] = 0ull;

#pragma unroll
                for (int kb = 0; kb < 12; kb++) {           // kb = d*4 + cq
                    const int d  = kb >> 2;
                    const int cq = kb & 3;
                    const ulonglong2 g0 = *(const ulonglong2*)&gp[(0 * 4 + cq) * 3 + d];
                    const ulonglong2 g1 = *(const ulonglong2*)&gp[(1 * 4 + cq) * 3 + d];
                    const ulonglong2 g2 = *(const ulonglong2*)&gp[(2 * 4 + cq) * 3 + d];
                    const ulonglong2 g3 = *(const ulonglong2*)&gp[(3 * 4 + cq) * 3 + d];
                    const u64 sx = add2(add2(g0.x, g1.x), add2(g2.x, g3.x));
                    const u64 sy = add2(add2(g0.y, g1.y), add2(g2.y, g3.y));
#pragma unroll
                    for (int oo = 0; oo < 8; oo++) {
                        const ulonglong2 wv = *(const ulonglong2*)&s_w2[kb][oh * 8 + oo];
                        fma2(acc[oo], wv.x, sx);
                        fma2(acc[oo], wv.y, sy);
                    }
                }

                float res[8];
#pragma unroll
                for (int oo = 0; oo < 8; oo++) {
                    const float2 f = upk2(acc[oo]);
                    res[oo] = f.x + f.y;
                }
                float4* op = (float4*)(out + (size_t)(base + pp2) * CO + oh * 8);
                op[0] = make_float4(res[0], res[1], res[2], res[3]);
                op[1] = make_float4(res[4], res[5], res[6], res[7]);
            }
        }
    }
}

extern "C" void kernel_launch(void* const* d_in, const int* in_sizes, int n_in,
                              void* d_out, int out_size) {
    const float* features = (const float*)d_in[0];
    const float* radii    = (const float*)d_in[1];
    const float* W        = (const float*)d_in[2];
    const int*   bs       = (const int*)d_in[3];
    float*       out      = (float*)d_out;

    const int P = in_sizes[0] / CI;
    const int blocks = (P + PTS_BLK - 1) / PTS_BLK;   // 1250 for P=40000
    PeriodicConvolutionPrep_fused<<<blocks, THREADS>>>(features, radii, W, bs, out, P);
}